// round 15
// baseline (speedup 1.0000x reference)
#include <cuda_runtime.h>

// ESN recurrence on GB300 — single-hop tagged-word exchange (settled protocol):
//   publish: st.relaxed.gpu.u64 {tag<<32|f32bits}  (strong 8B, tear-free)
//   poll:    ld.relaxed.gpu.u64 (strong => defined under race; weak polls are
//            UNDEFINED (R3/R7/R8); acquire chains serialize (R4)).
// R14 established: FFMA2 packed dot + tanh bounded to 2 lanes (MUFU rt=8!).
// R15: pipelined double-sample poll, now as a CLEAN single change on the R14
//      base (R12's regression was confounded by all-lanes tanh saturation).

#define H        1024
#define T        50000
#define WASHOUT  200
#define NOUT     (T - WASHOUT)   // 49800
#define B        128             // CTAs (<=148 SMs -> co-resident, spin-safe)
#define R        (H / B)         // 8 rows per CTA
#define THREADS  256             // 8 warps, 1 warp per row
#define NPART    1024

// Tagged state grouped by producer CTA: one 128B line per (buffer, producer).
__device__ __align__(128) unsigned long long g_xt[2][B][16];  // [0..7] used
__device__ float    g_coef[H];
__device__ unsigned g_epoch;
__device__ float    g_part[(size_t)NPART * NOUT];

static __device__ __forceinline__ unsigned long long pack_tv(unsigned tag, float v) {
    return ((unsigned long long)tag << 32) | (unsigned long long)__float_as_uint(v);
}
static __device__ __forceinline__ unsigned long long ld_rlx_u64(const unsigned long long* p) {
    unsigned long long v;
    asm volatile("ld.relaxed.gpu.global.u64 %0, [%1];" : "=l"(v) : "l"(p) : "memory");
    return v;
}
static __device__ __forceinline__ void st_rlx_u64(unsigned long long* p, unsigned long long v) {
    asm volatile("st.relaxed.gpu.global.u64 [%0], %1;" :: "l"(p), "l"(v) : "memory");
}
static __device__ __forceinline__ unsigned long long pack_f2(float lo, float hi) {
    unsigned long long r;
    asm("mov.b64 %0, {%1, %2};" : "=l"(r) : "f"(lo), "f"(hi));
    return r;
}
static __device__ __forceinline__ void unpack_f2(unsigned long long v, float& lo, float& hi) {
    asm("mov.b64 {%0, %1}, %2;" : "=f"(lo), "=f"(hi) : "l"(v));
}
static __device__ __forceinline__ void fma2(unsigned long long& d,
                                            unsigned long long a,
                                            unsigned long long b) {
    asm("fma.rn.f32x2 %0, %1, %2, %0;" : "+l"(d) : "l"(a), "l"(b));
}
// fast tanh: (e^{2x}-1)/(e^{2x}+1), MUFU.EX2+MUFU.RCP (~40cyc vs ~120 tanhf).
static __device__ __forceinline__ float fast_tanh(float x) {
    x = fminf(fmaxf(x, -20.0f), 20.0f);           // avoid inf/inf
    float t = __expf(2.0f * x);
    return __fdividef(t - 1.0f, t + 1.0f);
}

// ---------------------------------------------------------------------------
// Prologue: bump epoch, publish x0 = 0 (tag = base), build coef scatter.
// Mask dtype probed in parallel (int64 has >=512 zero odd int32 slots).
// ---------------------------------------------------------------------------
__global__ void esn_prologue(const float* __restrict__ w_out,
                             const void* __restrict__ mask_raw) {
    const int* m32 = (const int*)mask_raw;
    const int t = threadIdx.x;                    // 0..1023

    int is64 = __syncthreads_count(((t & 1) != 0) && (m32[t] == 0)) >= 256;
    if (t == 0) g_epoch = g_epoch + 1u;
    __syncthreads();
    const unsigned base = g_epoch * (unsigned)(T + 2);

    int idx;
    if (is64) idx = (int)((const long long*)mask_raw)[t];
    else      idx = m32[t];
    g_coef[idx & 1023] = w_out[t];
    g_xt[0][t >> 3][t & 7] = pack_tv(base, 0.0f); // x_0 = 0, tag = base
}

// ---------------------------------------------------------------------------
// Main persistent kernel. Warp w of CTA c owns row c*8+w (weights packed as
// f32x2 in 16 u64 regs/lane). Thread t consumes words [w0..w0+3] of producer
// p = t/2 (one 32B sector): pipelined double-sample relaxed poll, stage float4
// into double-buffered s_x, bar, FFMA2 dot, shfl butterfly, lanes 0-1 tanh;
// lane0 publishes, lane1 stores the readout partial.
// No trailing bar: staging bar of step k+1 gates s_x[buf] reuse at k+2.
// ---------------------------------------------------------------------------
__global__ void __launch_bounds__(THREADS, 1)
esn_main(const float* __restrict__ u,
         const float* __restrict__ w_in,
         const float* __restrict__ w_res) {
    __shared__ float s_x[2][H];                   // 8 KB, double-buffered

    const int tid  = threadIdx.x;
    const int warp = tid >> 5;
    const int lane = tid & 31;
    const int cta  = blockIdx.x;
    const int row  = cta * R + warp;
    const int p    = tid >> 1;                    // producer CTA of my float4
    const int w0   = (tid & 1) * 4;               // word offset within its line

    // Weights packed f32x2: lane l holds cols 4l+128j, j=0..7 (32 floats)
    unsigned long long wp[16];
    {
        const float4* wr = reinterpret_cast<const float4*>(w_res + (size_t)row * H);
        #pragma unroll
        for (int j = 0; j < 8; ++j) {
            float4 w = __ldg(wr + lane + 32 * j);
            wp[2 * j + 0] = pack_f2(w.x, w.y);
            wp[2 * j + 1] = pack_f2(w.z, w.w);
        }
    }
    const float my_win  = w_in[row];
    const float my_coef = g_coef[row];
    const unsigned base = g_epoch * (unsigned)(T + 2);
    float* part_row = &g_part[(size_t)row * NOUT];

    const unsigned long long* gx[2] = { &g_xt[0][p][w0], &g_xt[1][p][w0] };
    unsigned long long* mypub[2] = { &g_xt[0][cta][warp], &g_xt[1][cta][warp] };

    for (int k = 0; k < T; ++k) {
        const float uk = __ldg(u + k);            // issues early, used at tanh
        const unsigned want = base + (unsigned)k;
        const int buf = k & 1;
        const unsigned long long* g = gx[buf];

        // ---- pipelined poll: two alternating 4-word samples in flight ------
        unsigned long long v0, v1, v2, v3, q0, q1, q2, q3;
        v0 = ld_rlx_u64(g + 0); v1 = ld_rlx_u64(g + 1);
        v2 = ld_rlx_u64(g + 2); v3 = ld_rlx_u64(g + 3);
        for (;;) {
            q0 = ld_rlx_u64(g + 0); q1 = ld_rlx_u64(g + 1);   // next sample
            q2 = ld_rlx_u64(g + 2); q3 = ld_rlx_u64(g + 3);   // already in pipe
            if ((unsigned)(v0 >> 32) == want && (unsigned)(v1 >> 32) == want &&
                (unsigned)(v2 >> 32) == want && (unsigned)(v3 >> 32) == want)
                break;
            v0 = ld_rlx_u64(g + 0); v1 = ld_rlx_u64(g + 1);   // third sample
            v2 = ld_rlx_u64(g + 2); v3 = ld_rlx_u64(g + 3);
            if ((unsigned)(q0 >> 32) == want && (unsigned)(q1 >> 32) == want &&
                (unsigned)(q2 >> 32) == want && (unsigned)(q3 >> 32) == want) {
                v0 = q0; v1 = q1; v2 = q2; v3 = q3;
                break;
            }
        }

        float4 xv;
        xv.x = __uint_as_float((unsigned)v0);
        xv.y = __uint_as_float((unsigned)v1);
        xv.z = __uint_as_float((unsigned)v2);
        xv.w = __uint_as_float((unsigned)v3);
        reinterpret_cast<float4*>(s_x[buf])[tid] = xv;
        __syncthreads();                          // all 1024 values staged

        // ---- FFMA2 dot product: 16 fma.rn.f32x2, 4 independent chains ------
        const float4* xr = reinterpret_cast<const float4*>(s_x[buf]);
        unsigned long long A0 = 0ull, A1 = 0ull, A2 = 0ull, A3 = 0ull;
        #pragma unroll
        for (int j = 0; j < 8; j += 2) {
            float4 xa = xr[lane + 32 * (j + 0)];
            float4 xb = xr[lane + 32 * (j + 1)];
            fma2(A0, wp[2 * j + 0], pack_f2(xa.x, xa.y));
            fma2(A1, wp[2 * j + 1], pack_f2(xa.z, xa.w));
            fma2(A2, wp[2 * j + 2], pack_f2(xb.x, xb.y));
            fma2(A3, wp[2 * j + 3], pack_f2(xb.z, xb.w));
        }
        float f0, f1, f2, f3, f4, f5, f6, f7;
        unpack_f2(A0, f0, f1); unpack_f2(A1, f2, f3);
        unpack_f2(A2, f4, f5); unpack_f2(A3, f6, f7);
        float acc = ((f0 + f1) + (f2 + f3)) + ((f4 + f5) + (f6 + f7));
        #pragma unroll
        for (int off = 16; off > 0; off >>= 1)      // butterfly: sum in ALL lanes
            acc += __shfl_xor_sync(0xffffffffu, acc, off);

        if (lane < 2) {                             // MUFU bounded to 2 lanes
            const float val = fast_tanh(fmaf(my_win, uk, acc));
            if (lane == 0)                          // publish on shortest path
                st_rlx_u64(mypub[buf ^ 1], pack_tv(want + 1u, val));
            else if (k >= WASHOUT)                  // readout off publish path
                part_row[k - WASHOUT] = val * my_coef;
        }
        // no trailing bar: s_x[buf] reuse at k+2 is gated by k+1's staging bar
    }
}

// ---------------------------------------------------------------------------
// Finalize: deterministic fixed-order reduction of 1024 per-row partials.
// ---------------------------------------------------------------------------
__global__ void esn_finalize(float* __restrict__ out) {
    int t = blockIdx.x * blockDim.x + threadIdx.x;
    if (t < NOUT) {
        float s = 0.0f;
        #pragma unroll 8
        for (int r = 0; r < NPART; ++r)
            s += g_part[(size_t)r * NOUT + t];    // coalesced across threads
        out[t] = s;
    }
}

// ---------------------------------------------------------------------------
// Inputs (metadata order): u[50000] f32, w_in[1024] f32, w_res[1024*1024] f32,
// w_out[1024] f32, w_out_mask[1024] int (32/64 probed). Output: 49800 f32.
// ---------------------------------------------------------------------------
extern "C" void kernel_launch(void* const* d_in, const int* in_sizes, int n_in,
                              void* d_out, int out_size) {
    const float* u     = (const float*)d_in[0];
    const float* w_in  = (const float*)d_in[1];
    const float* w_res = (const float*)d_in[2];
    const float* w_out = (const float*)d_in[3];
    const void*  mask  = d_in[4];
    float*       out   = (float*)d_out;

    esn_prologue<<<1, 1024>>>(w_out, mask);
    esn_main<<<B, THREADS>>>(u, w_in, w_res);
    esn_finalize<<<(NOUT + 255) / 256, 256>>>(out);
}

// round 16
// speedup vs baseline: 1.8079x; 1.8079x over previous
#include <cuda_runtime.h>

// ESN recurrence on GB300 — single-hop tagged-word exchange. SETTLED LAWS:
//  * publish: st.relaxed.gpu.u64 {tag<<32|f32bits} (strong 8B, tear-free)
//  * poll:    ld.relaxed.gpu.u64, DEPENDENT single-sample loop. Weak polls =
//    UNDEFINED under race (R3/R7/R8). Acquire chains serialize (R4).
//    Oversampling floods the per-SM LSU FIFO and delays its own publish/
//    detect (R12/R15: +53ms). Backoff delays detection (R13: +6.5ms).
//  * FFMA2 packed dot + MUFU bounded to 2 lanes + lane-split epilogue (R14).
// R16: drop tanh clamp (|arg|<=~28 provably safe), prefetch u one step ahead.

#define H        1024
#define T        50000
#define WASHOUT  200
#define NOUT     (T - WASHOUT)   // 49800
#define B        128             // CTAs (<=148 SMs -> co-resident, spin-safe)
#define R        (H / B)         // 8 rows per CTA
#define THREADS  256             // 8 warps, 1 warp per row
#define NPART    1024

// Tagged state grouped by producer CTA: one 128B line per (buffer, producer).
__device__ __align__(128) unsigned long long g_xt[2][B][16];  // [0..7] used
__device__ float    g_coef[H];
__device__ unsigned g_epoch;
__device__ float    g_part[(size_t)NPART * NOUT];

static __device__ __forceinline__ unsigned long long pack_tv(unsigned tag, float v) {
    return ((unsigned long long)tag << 32) | (unsigned long long)__float_as_uint(v);
}
static __device__ __forceinline__ unsigned long long ld_rlx_u64(const unsigned long long* p) {
    unsigned long long v;
    asm volatile("ld.relaxed.gpu.global.u64 %0, [%1];" : "=l"(v) : "l"(p) : "memory");
    return v;
}
static __device__ __forceinline__ void st_rlx_u64(unsigned long long* p, unsigned long long v) {
    asm volatile("st.relaxed.gpu.global.u64 [%0], %1;" :: "l"(p), "l"(v) : "memory");
}
static __device__ __forceinline__ unsigned long long pack_f2(float lo, float hi) {
    unsigned long long r;
    asm("mov.b64 %0, {%1, %2};" : "=l"(r) : "f"(lo), "f"(hi));
    return r;
}
static __device__ __forceinline__ void unpack_f2(unsigned long long v, float& lo, float& hi) {
    asm("mov.b64 {%0, %1}, %2;" : "=f"(lo), "=f"(hi) : "l"(v));
}
static __device__ __forceinline__ void fma2(unsigned long long& d,
                                            unsigned long long a,
                                            unsigned long long b) {
    asm("fma.rn.f32x2 %0, %1, %2, %0;" : "+l"(d) : "l"(a), "l"(b));
}
// fast tanh: (e^{2x}-1)/(e^{2x}+1). No clamp: |arg| <= ||w_row||_1 + |w_in*u|
// ~ 28 => e^{2x} <= ~2e24, finite in f32. MUFU.EX2+MUFU.RCP (~40cyc).
static __device__ __forceinline__ float fast_tanh(float x) {
    float t = __expf(2.0f * x);
    return __fdividef(t - 1.0f, t + 1.0f);
}

// ---------------------------------------------------------------------------
// Prologue: bump epoch, publish x0 = 0 (tag = base), build coef scatter.
// Mask dtype probed in parallel (int64 has >=512 zero odd int32 slots).
// ---------------------------------------------------------------------------
__global__ void esn_prologue(const float* __restrict__ w_out,
                             const void* __restrict__ mask_raw) {
    const int* m32 = (const int*)mask_raw;
    const int t = threadIdx.x;                    // 0..1023

    int is64 = __syncthreads_count(((t & 1) != 0) && (m32[t] == 0)) >= 256;
    if (t == 0) g_epoch = g_epoch + 1u;
    __syncthreads();
    const unsigned base = g_epoch * (unsigned)(T + 2);

    int idx;
    if (is64) idx = (int)((const long long*)mask_raw)[t];
    else      idx = m32[t];
    g_coef[idx & 1023] = w_out[t];
    g_xt[0][t >> 3][t & 7] = pack_tv(base, 0.0f); // x_0 = 0, tag = base
}

// ---------------------------------------------------------------------------
// Main persistent kernel. Warp w of CTA c owns row c*8+w (weights packed as
// f32x2 in 16 u64 regs/lane). Thread t consumes words [w0..w0+3] of producer
// p = t/2 (one 32B sector): dependent single-sample relaxed poll, stage float4
// into double-buffered s_x, bar, FFMA2 dot, shfl butterfly, lanes 0-1 tanh;
// lane0 publishes, lane1 stores the readout partial.
// No trailing bar: staging bar of step k+1 gates s_x[buf] reuse at k+2.
// ---------------------------------------------------------------------------
__global__ void __launch_bounds__(THREADS, 1)
esn_main(const float* __restrict__ u,
         const float* __restrict__ w_in,
         const float* __restrict__ w_res) {
    __shared__ float s_x[2][H];                   // 8 KB, double-buffered

    const int tid  = threadIdx.x;
    const int warp = tid >> 5;
    const int lane = tid & 31;
    const int cta  = blockIdx.x;
    const int row  = cta * R + warp;
    const int p    = tid >> 1;                    // producer CTA of my float4
    const int w0   = (tid & 1) * 4;               // word offset within its line

    // Weights packed f32x2: lane l holds cols 4l+128j, j=0..7 (32 floats)
    unsigned long long wp[16];
    {
        const float4* wr = reinterpret_cast<const float4*>(w_res + (size_t)row * H);
        #pragma unroll
        for (int j = 0; j < 8; ++j) {
            float4 w = __ldg(wr + lane + 32 * j);
            wp[2 * j + 0] = pack_f2(w.x, w.y);
            wp[2 * j + 1] = pack_f2(w.z, w.w);
        }
    }
    const float my_win  = w_in[row];
    const float my_coef = g_coef[row];
    const unsigned base = g_epoch * (unsigned)(T + 2);
    float* part_row = &g_part[(size_t)row * NOUT];

    const unsigned long long* gx[2] = { &g_xt[0][p][w0], &g_xt[1][p][w0] };
    unsigned long long* mypub[2] = { &g_xt[0][cta][warp], &g_xt[1][cta][warp] };

    float uk = __ldg(u);                          // u[0] preloaded

    for (int k = 0; k < T; ++k) {
        const float uk_next = (k + 1 < T) ? __ldg(u + k + 1) : 0.0f;  // prefetch
        const unsigned want = base + (unsigned)k;
        const int buf = k & 1;
        const unsigned long long* g = gx[buf];

        // ---- dependent single-sample poll (the settled optimum) ------------
        unsigned long long v0, v1, v2, v3;
        for (;;) {
            v0 = ld_rlx_u64(g + 0);
            v1 = ld_rlx_u64(g + 1);
            v2 = ld_rlx_u64(g + 2);
            v3 = ld_rlx_u64(g + 3);
            if ((unsigned)(v0 >> 32) == want && (unsigned)(v1 >> 32) == want &&
                (unsigned)(v2 >> 32) == want && (unsigned)(v3 >> 32) == want)
                break;
        }

        float4 xv;
        xv.x = __uint_as_float((unsigned)v0);
        xv.y = __uint_as_float((unsigned)v1);
        xv.z = __uint_as_float((unsigned)v2);
        xv.w = __uint_as_float((unsigned)v3);
        reinterpret_cast<float4*>(s_x[buf])[tid] = xv;
        __syncthreads();                          // all 1024 values staged

        // ---- FFMA2 dot product: 16 fma.rn.f32x2, 4 independent chains ------
        const float4* xr = reinterpret_cast<const float4*>(s_x[buf]);
        unsigned long long A0 = 0ull, A1 = 0ull, A2 = 0ull, A3 = 0ull;
        #pragma unroll
        for (int j = 0; j < 8; j += 2) {
            float4 xa = xr[lane + 32 * (j + 0)];
            float4 xb = xr[lane + 32 * (j + 1)];
            fma2(A0, wp[2 * j + 0], pack_f2(xa.x, xa.y));
            fma2(A1, wp[2 * j + 1], pack_f2(xa.z, xa.w));
            fma2(A2, wp[2 * j + 2], pack_f2(xb.x, xb.y));
            fma2(A3, wp[2 * j + 3], pack_f2(xb.z, xb.w));
        }
        float f0, f1, f2, f3, f4, f5, f6, f7;
        unpack_f2(A0, f0, f1); unpack_f2(A1, f2, f3);
        unpack_f2(A2, f4, f5); unpack_f2(A3, f6, f7);
        float acc = ((f0 + f1) + (f2 + f3)) + ((f4 + f5) + (f6 + f7));
        #pragma unroll
        for (int off = 16; off > 0; off >>= 1)      // butterfly: sum in ALL lanes
            acc += __shfl_xor_sync(0xffffffffu, acc, off);

        if (lane < 2) {                             // MUFU bounded to 2 lanes
            const float val = fast_tanh(fmaf(my_win, uk, acc));
            if (lane == 0)                          // publish on shortest path
                st_rlx_u64(mypub[buf ^ 1], pack_tv(want + 1u, val));
            else if (k >= WASHOUT)                  // readout off publish path
                part_row[k - WASHOUT] = val * my_coef;
        }
        uk = uk_next;
        // no trailing bar: s_x[buf] reuse at k+2 is gated by k+1's staging bar
    }
}

// ---------------------------------------------------------------------------
// Finalize: deterministic fixed-order reduction of 1024 per-row partials.
// ---------------------------------------------------------------------------
__global__ void esn_finalize(float* __restrict__ out) {
    int t = blockIdx.x * blockDim.x + threadIdx.x;
    if (t < NOUT) {
        float s = 0.0f;
        #pragma unroll 8
        for (int r = 0; r < NPART; ++r)
            s += g_part[(size_t)r * NOUT + t];    // coalesced across threads
        out[t] = s;
    }
}

// ---------------------------------------------------------------------------
// Inputs (metadata order): u[50000] f32, w_in[1024] f32, w_res[1024*1024] f32,
// w_out[1024] f32, w_out_mask[1024] int (32/64 probed). Output: 49800 f32.
// ---------------------------------------------------------------------------
extern "C" void kernel_launch(void* const* d_in, const int* in_sizes, int n_in,
                              void* d_out, int out_size) {
    const float* u     = (const float*)d_in[0];
    const float* w_in  = (const float*)d_in[1];
    const float* w_res = (const float*)d_in[2];
    const float* w_out = (const float*)d_in[3];
    const void*  mask  = d_in[4];
    float*       out   = (float*)d_out;

    esn_prologue<<<1, 1024>>>(w_out, mask);
    esn_main<<<B, THREADS>>>(u, w_in, w_res);
    esn_finalize<<<(NOUT + 255) / 256, 256>>>(out);
}

// round 17
// speedup vs baseline: 2.5081x; 1.3873x over previous
#include <cuda_runtime.h>

// ESN recurrence on GB300 — single-hop tagged-word exchange. SETTLED LAWS:
//  * publish: st.relaxed.gpu.u64 {tag<<32|f32bits} (strong 8B, tear-free)
//  * poll:    ld.relaxed.gpu.u64, DEPENDENT single-sample loop (weak=UNDEFINED
//    R3/R7/R8; acquire chains serialize R4; oversampling floods LSU R12/R15;
//    backoff delays detection R13).
//  * FFMA2 packed dot + MUFU bounded to 2 lanes + lane-split epilogue (R14).
// R17: wavefront-coalesced poll. Flat unpadded mailbox g_xt[2][1024]; thread t
//      polls words {t, t+256, t+512, t+768} -> each poll LDG covers 32
//      consecutive words (256B = 2 wavefronts vs 16 scattered before): per-SM
//      L1tex wavefront load per poll round drops 512 -> 64.

#define H        1024
#define T        50000
#define WASHOUT  200
#define NOUT     (T - WASHOUT)   // 49800
#define B        128             // CTAs (<=148 SMs -> co-resident, spin-safe)
#define R        (H / B)         // 8 rows per CTA
#define THREADS  256             // 8 warps, 1 warp per row
#define NPART    1024

// Flat tagged state: word h belongs to producer h>>3 (64B per producer,
// sector-aligned: no 32B-sector sharing between producers' publishes).
__device__ __align__(128) unsigned long long g_xt[2][H];
__device__ float    g_coef[H];
__device__ unsigned g_epoch;
__device__ float    g_part[(size_t)NPART * NOUT];

static __device__ __forceinline__ unsigned long long pack_tv(unsigned tag, float v) {
    return ((unsigned long long)tag << 32) | (unsigned long long)__float_as_uint(v);
}
static __device__ __forceinline__ unsigned long long ld_rlx_u64(const unsigned long long* p) {
    unsigned long long v;
    asm volatile("ld.relaxed.gpu.global.u64 %0, [%1];" : "=l"(v) : "l"(p) : "memory");
    return v;
}
static __device__ __forceinline__ void st_rlx_u64(unsigned long long* p, unsigned long long v) {
    asm volatile("st.relaxed.gpu.global.u64 [%0], %1;" :: "l"(p), "l"(v) : "memory");
}
static __device__ __forceinline__ unsigned long long pack_f2(float lo, float hi) {
    unsigned long long r;
    asm("mov.b64 %0, {%1, %2};" : "=l"(r) : "f"(lo), "f"(hi));
    return r;
}
static __device__ __forceinline__ void unpack_f2(unsigned long long v, float& lo, float& hi) {
    asm("mov.b64 {%0, %1}, %2;" : "=f"(lo), "=f"(hi) : "l"(v));
}
static __device__ __forceinline__ void fma2(unsigned long long& d,
                                            unsigned long long a,
                                            unsigned long long b) {
    asm("fma.rn.f32x2 %0, %1, %2, %0;" : "+l"(d) : "l"(a), "l"(b));
}
// fast tanh: (e^{2x}-1)/(e^{2x}+1). No clamp: |arg| <= ~28 => finite in f32.
static __device__ __forceinline__ float fast_tanh(float x) {
    float t = __expf(2.0f * x);
    return __fdividef(t - 1.0f, t + 1.0f);
}

// ---------------------------------------------------------------------------
// Prologue: bump epoch, publish x0 = 0 (tag = base), build coef scatter.
// Mask dtype probed in parallel (int64 has >=512 zero odd int32 slots).
// ---------------------------------------------------------------------------
__global__ void esn_prologue(const float* __restrict__ w_out,
                             const void* __restrict__ mask_raw) {
    const int* m32 = (const int*)mask_raw;
    const int t = threadIdx.x;                    // 0..1023

    int is64 = __syncthreads_count(((t & 1) != 0) && (m32[t] == 0)) >= 256;
    if (t == 0) g_epoch = g_epoch + 1u;
    __syncthreads();
    const unsigned base = g_epoch * (unsigned)(T + 2);

    int idx;
    if (is64) idx = (int)((const long long*)mask_raw)[t];
    else      idx = m32[t];
    g_coef[idx & 1023] = w_out[t];
    g_xt[0][t] = pack_tv(base, 0.0f);             // x_0 = 0, tag = base
}

// ---------------------------------------------------------------------------
// Main persistent kernel. Warp w of CTA c owns row c*8+w (weights packed as
// f32x2 in 16 u64 regs/lane). Thread t polls words {t,t+256,t+512,t+768}
// (each LDG warp-coalesced: 256B = 2 wavefronts), stages 4 scalar floats into
// double-buffered s_x, bar, FFMA2 dot, shfl butterfly, lanes 0-1 tanh;
// lane0 publishes word `row`, lane1 stores the readout partial.
// No trailing bar: staging bar of step k+1 gates s_x[buf] reuse at k+2.
// ---------------------------------------------------------------------------
__global__ void __launch_bounds__(THREADS, 1)
esn_main(const float* __restrict__ u,
         const float* __restrict__ w_in,
         const float* __restrict__ w_res) {
    __shared__ float s_x[2][H];                   // 8 KB, double-buffered

    const int tid  = threadIdx.x;
    const int warp = tid >> 5;
    const int lane = tid & 31;
    const int cta  = blockIdx.x;
    const int row  = cta * R + warp;

    // Weights packed f32x2: lane l holds cols 4l+128j, j=0..7 (32 floats)
    unsigned long long wp[16];
    {
        const float4* wr = reinterpret_cast<const float4*>(w_res + (size_t)row * H);
        #pragma unroll
        for (int j = 0; j < 8; ++j) {
            float4 w = __ldg(wr + lane + 32 * j);
            wp[2 * j + 0] = pack_f2(w.x, w.y);
            wp[2 * j + 1] = pack_f2(w.z, w.w);
        }
    }
    const float my_win  = w_in[row];
    const float my_coef = g_coef[row];
    const unsigned base = g_epoch * (unsigned)(T + 2);
    float* part_row = &g_part[(size_t)row * NOUT];

    const unsigned long long* gx[2] = { &g_xt[0][tid], &g_xt[1][tid] };
    unsigned long long* mypub[2] = { &g_xt[0][row], &g_xt[1][row] };

    float uk = __ldg(u);                          // u[0] preloaded

    for (int k = 0; k < T; ++k) {
        const float uk_next = (k + 1 < T) ? __ldg(u + k + 1) : 0.0f;  // prefetch
        const unsigned want = base + (unsigned)k;
        const int buf = k & 1;
        const unsigned long long* g = gx[buf];

        // ---- dependent single-sample poll, warp-coalesced words -----------
        unsigned long long v0, v1, v2, v3;
        for (;;) {
            v0 = ld_rlx_u64(g + 0);
            v1 = ld_rlx_u64(g + 256);
            v2 = ld_rlx_u64(g + 512);
            v3 = ld_rlx_u64(g + 768);
            if ((unsigned)(v0 >> 32) == want && (unsigned)(v1 >> 32) == want &&
                (unsigned)(v2 >> 32) == want && (unsigned)(v3 >> 32) == want)
                break;
        }
        s_x[buf][tid      ] = __uint_as_float((unsigned)v0);
        s_x[buf][tid + 256] = __uint_as_float((unsigned)v1);
        s_x[buf][tid + 512] = __uint_as_float((unsigned)v2);
        s_x[buf][tid + 768] = __uint_as_float((unsigned)v3);
        __syncthreads();                          // all 1024 values staged

        // ---- FFMA2 dot product: 16 fma.rn.f32x2, 4 independent chains ------
        const float4* xr = reinterpret_cast<const float4*>(s_x[buf]);
        unsigned long long A0 = 0ull, A1 = 0ull, A2 = 0ull, A3 = 0ull;
        #pragma unroll
        for (int j = 0; j < 8; j += 2) {
            float4 xa = xr[lane + 32 * (j + 0)];
            float4 xb = xr[lane + 32 * (j + 1)];
            fma2(A0, wp[2 * j + 0], pack_f2(xa.x, xa.y));
            fma2(A1, wp[2 * j + 1], pack_f2(xa.z, xa.w));
            fma2(A2, wp[2 * j + 2], pack_f2(xb.x, xb.y));
            fma2(A3, wp[2 * j + 3], pack_f2(xb.z, xb.w));
        }
        float f0, f1, f2, f3, f4, f5, f6, f7;
        unpack_f2(A0, f0, f1); unpack_f2(A1, f2, f3);
        unpack_f2(A2, f4, f5); unpack_f2(A3, f6, f7);
        float acc = ((f0 + f1) + (f2 + f3)) + ((f4 + f5) + (f6 + f7));
        #pragma unroll
        for (int off = 16; off > 0; off >>= 1)      // butterfly: sum in ALL lanes
            acc += __shfl_xor_sync(0xffffffffu, acc, off);

        if (lane < 2) {                             // MUFU bounded to 2 lanes
            const float val = fast_tanh(fmaf(my_win, uk, acc));
            if (lane == 0)                          // publish on shortest path
                st_rlx_u64(mypub[buf ^ 1], pack_tv(want + 1u, val));
            else if (k >= WASHOUT)                  // readout off publish path
                part_row[k - WASHOUT] = val * my_coef;
        }
        uk = uk_next;
        // no trailing bar: s_x[buf] reuse at k+2 is gated by k+1's staging bar
    }
}

// ---------------------------------------------------------------------------
// Finalize: deterministic fixed-order reduction of 1024 per-row partials.
// ---------------------------------------------------------------------------
__global__ void esn_finalize(float* __restrict__ out) {
    int t = blockIdx.x * blockDim.x + threadIdx.x;
    if (t < NOUT) {
        float s = 0.0f;
        #pragma unroll 8
        for (int r = 0; r < NPART; ++r)
            s += g_part[(size_t)r * NOUT + t];    // coalesced across threads
        out[t] = s;
    }
}

// ---------------------------------------------------------------------------
// Inputs (metadata order): u[50000] f32, w_in[1024] f32, w_res[1024*1024] f32,
// w_out[1024] f32, w_out_mask[1024] int (32/64 probed). Output: 49800 f32.
// ---------------------------------------------------------------------------
extern "C" void kernel_launch(void* const* d_in, const int* in_sizes, int n_in,
                              void* d_out, int out_size) {
    const float* u     = (const float*)d_in[0];
    const float* w_in  = (const float*)d_in[1];
    const float* w_res = (const float*)d_in[2];
    const float* w_out = (const float*)d_in[3];
    const void*  mask  = d_in[4];
    float*       out   = (float*)d_out;

    esn_prologue<<<1, 1024>>>(w_out, mask);
    esn_main<<<B, THREADS>>>(u, w_in, w_res);
    esn_finalize<<<(NOUT + 255) / 256, 256>>>(out);
}